// round 13
// baseline (speedup 1.0000x reference)
#include <cuda_runtime.h>
#include <cstdint>

// ---------------------------------------------------------------------------
// Problem dims
// ---------------------------------------------------------------------------
#define TSTEPS 512
#define NB     64
#define HID    256
#define MROWS  (TSTEPS * NB)      // 32768
#define NCOLS  1024               // 4*HID
#define KDIM   256
#define NCLASS 5

#define GRID_REC 128
#define NJ   32                    // j per CTA
#define NBL  8                     // batches per CTA/group
#define NPROD 8                    // producers per group
#define SHS  260                   // s_h row stride (floats)
#define FULLMASK 0xffffffffu
#define REC_SMEM ((NJ * 4 * KDIM + NBL * SHS) * 4)   // 128KB U + 8.3KB h

// ---------------------------------------------------------------------------
// Scratch (static __device__ arrays: allocation-free, allowed)
// ---------------------------------------------------------------------------
__device__ __align__(128) float g_Z [2u * MROWS * NCOLS];   // gate preactivations
__device__ __align__(128) float g_H1[2u * MROWS * HID];     // layer-1 hidden outputs
__device__ __align__(128) float g_H2[2u * MROWS * HID];     // layer-2 hidden outputs
__device__ __align__(128) float g_hT[2][2][NB * HID];       // dbl-buf h, [parity][dir][b][j]
__device__ __align__(128) unsigned g_flags[2][16][NPROD];   // [layer][group][producer jb]
__device__ int g_tok32 = 1;                                 // token dtype flag

// ---------------------------------------------------------------------------
// Message passing + async-copy primitives
// ---------------------------------------------------------------------------
__device__ __forceinline__ unsigned ld_acquire(const unsigned* p) {
    unsigned v;
    asm volatile("ld.acquire.gpu.global.u32 %0, [%1];" : "=r"(v) : "l"(p) : "memory");
    return v;
}
__device__ __forceinline__ void st_release(unsigned* p, unsigned v) {
    asm volatile("st.release.gpu.global.u32 [%0], %1;" :: "l"(p), "r"(v) : "memory");
}
#define CP_ASYNC16(dst_u32, src_ptr) \
    asm volatile("cp.async.cg.shared.global [%0], [%1], 16;" :: "r"(dst_u32), "l"(src_ptr))
#define CP_COMMIT() asm volatile("cp.async.commit_group;" ::: "memory")
#define CP_WAIT0()  asm volatile("cp.async.wait_group 0;" ::: "memory")

// ---------------------------------------------------------------------------
// Math helpers
// ---------------------------------------------------------------------------
__device__ __forceinline__ float fsig(float x) {
    x = fminf(fmaxf(x, -30.f), 30.f);
    return __fdividef(1.f, 1.f + __expf(-x));
}
__device__ __forceinline__ float ftanh_(float x) {
    x = fminf(fmaxf(x, -15.f), 15.f);
    float e = __expf(-2.f * x);
    return __fdividef(1.f - e, 1.f + e);
}
__device__ __forceinline__ int load_token(const void* tokens, int is32, int idx) {
    if (is32) return ((const int*)tokens)[idx];
    return (int)((const long long*)tokens)[idx];
}

// ---------------------------------------------------------------------------
// Prep: zero flags (graph replays) + token dtype probe.
// ---------------------------------------------------------------------------
__global__ void prep_kernel(const void* __restrict__ tokens) {
    __shared__ int flag;
    const int tid = threadIdx.x;
    if (tid < 2 * 16 * NPROD) ((unsigned*)g_flags)[tid] = 0u;
    if (tid == 0) flag = 0;
    __syncthreads();
    const int* p = (const int*)tokens;
    int local = 0;
    for (int i = 1 + 2 * tid; i < MROWS; i += 2 * 256) local |= p[i];
    if (local) atomicOr(&flag, 1);
    __syncthreads();
    if (tid == 0) g_tok32 = (flag != 0) ? 1 : 0;
}

// ---------------------------------------------------------------------------
// SGEMM, software-pipelined: C[dir] = A @ W[dir] + bias[dir]
// B-tile: cp.async double-buffer (row layout matches 16B copies).
// A-tile: register prefetch (LDG t+1 while computing t, STS to other buffer).
// One __syncthreads per k-tile; loads hidden under the FFMA block.
// ---------------------------------------------------------------------------
__global__ void __launch_bounds__(256, 2) gemm_kernel(
    const float* __restrict__ embed,
    const void*  __restrict__ tokens,
    const float* __restrict__ W_fw,
    const float* __restrict__ W_bw,
    const float* __restrict__ b_fw,
    const float* __restrict__ b_bw,
    int mode)
{
    __shared__ __align__(16) float As[2][16][132];
    __shared__ __align__(16) float Bs[2][16][128];
    __shared__ int sTok[128];

    const int tid = threadIdx.x;
    const int dir = blockIdx.z;
    const int m0  = blockIdx.y * 128;
    const int n0  = blockIdx.x * 128;

    const float* Wm   = dir ? W_bw : W_fw;
    const float* bias = dir ? b_bw : b_fw;

    if (mode == 0 && tid < 128) {
        int r = m0 + tid;
        int s = r >> 6, b = r & 63;
        int tt = (dir == 0) ? s : (TSTEPS - 1 - s);
        sTok[tid] = load_token(tokens, g_tok32, b * TSTEPS + tt);
    }
    __syncthreads();

    const int ty = tid >> 4;
    const int tx = tid & 15;

    // per-thread A-load coords (2 float4s per tile)
    const int am0  = tid >> 2,          akq0 = tid & 3;
    const int am1  = (tid + 256) >> 2,  akq1 = (tid + 256) & 3;
    const float* arow0;
    const float* arow1;
    if (mode == 0) {
        arow0 = embed + (size_t)sTok[am0] * KDIM;
        arow1 = embed + (size_t)sTok[am1] * KDIM;
    } else {
        const float* base = g_H1 + (size_t)dir * MROWS * HID;
        arow0 = base + (size_t)(m0 + am0) * HID;
        arow1 = base + (size_t)(m0 + am1) * HID;
    }

    // per-thread B cp.async coords (2 16B copies per tile)
    const int bk0 = tid >> 5,          bn0 = tid & 31;
    const int bk1 = (tid + 256) >> 5,  bn1 = (tid + 256) & 31;
    const uint32_t bs0_base = (uint32_t)__cvta_generic_to_shared(&Bs[0][bk0][bn0 * 4]);
    const uint32_t bs1_base = (uint32_t)__cvta_generic_to_shared(&Bs[0][bk1][bn1 * 4]);
    const uint32_t bufstride = (uint32_t)(16 * 128 * 4);
    const float* bsrc0 = Wm + (size_t)bk0 * NCOLS + n0 + bn0 * 4;
    const float* bsrc1 = Wm + (size_t)bk1 * NCOLS + n0 + bn1 * 4;

    float acc[8][8];
#pragma unroll
    for (int i = 0; i < 8; i++)
#pragma unroll
        for (int j = 0; j < 8; j++) acc[i][j] = 0.f;

    // ---- prologue: tile 0 ----
    CP_ASYNC16(bs0_base, bsrc0);
    CP_ASYNC16(bs1_base, bsrc1);
    CP_COMMIT();
    {
        float4 a0 = *(const float4*)(arow0 + akq0 * 4);
        float4 a1 = *(const float4*)(arow1 + akq1 * 4);
        As[0][akq0 * 4 + 0][am0] = a0.x; As[0][akq0 * 4 + 1][am0] = a0.y;
        As[0][akq0 * 4 + 2][am0] = a0.z; As[0][akq0 * 4 + 3][am0] = a0.w;
        As[0][akq1 * 4 + 0][am1] = a1.x; As[0][akq1 * 4 + 1][am1] = a1.y;
        As[0][akq1 * 4 + 2][am1] = a1.z; As[0][akq1 * 4 + 3][am1] = a1.w;
    }
    CP_WAIT0();
    __syncthreads();

    for (int t = 0; t < 16; t++) {
        const int buf  = t & 1;
        const int nbuf = buf ^ 1;
        float4 a0, a1;
        const bool more = (t + 1 < 16);
        if (more) {
            const int kt = (t + 1) * 16;
            CP_ASYNC16(bs0_base + (uint32_t)nbuf * bufstride, bsrc0 + (size_t)kt * NCOLS);
            CP_ASYNC16(bs1_base + (uint32_t)nbuf * bufstride, bsrc1 + (size_t)kt * NCOLS);
            CP_COMMIT();
            a0 = *(const float4*)(arow0 + kt + akq0 * 4);
            a1 = *(const float4*)(arow1 + kt + akq1 * 4);
        }

#pragma unroll
        for (int kk = 0; kk < 16; kk++) {
            float a[8], bb[8];
            *(float4*)&a[0]  = *(const float4*)&As[buf][kk][ty * 8];
            *(float4*)&a[4]  = *(const float4*)&As[buf][kk][ty * 8 + 4];
            *(float4*)&bb[0] = *(const float4*)&Bs[buf][kk][tx * 8];
            *(float4*)&bb[4] = *(const float4*)&Bs[buf][kk][tx * 8 + 4];
#pragma unroll
            for (int i = 0; i < 8; i++)
#pragma unroll
                for (int j = 0; j < 8; j++)
                    acc[i][j] = fmaf(a[i], bb[j], acc[i][j]);
        }

        if (more) {
            As[nbuf][akq0 * 4 + 0][am0] = a0.x; As[nbuf][akq0 * 4 + 1][am0] = a0.y;
            As[nbuf][akq0 * 4 + 2][am0] = a0.z; As[nbuf][akq0 * 4 + 3][am0] = a0.w;
            As[nbuf][akq1 * 4 + 0][am1] = a1.x; As[nbuf][akq1 * 4 + 1][am1] = a1.y;
            As[nbuf][akq1 * 4 + 2][am1] = a1.z; As[nbuf][akq1 * 4 + 3][am1] = a1.w;
            CP_WAIT0();
        }
        __syncthreads();
    }

    float bv[8];
#pragma unroll
    for (int j = 0; j < 8; j++) bv[j] = bias[n0 + tx * 8 + j];

    float* Cd = g_Z + (size_t)dir * MROWS * NCOLS;
#pragma unroll
    for (int i = 0; i < 8; i++) {
        size_t r = (size_t)(m0 + ty * 8 + i);
        float* cp = Cd + r * NCOLS + n0 + tx * 8;
        float4 o0, o1;
        o0.x = acc[i][0] + bv[0]; o0.y = acc[i][1] + bv[1];
        o0.z = acc[i][2] + bv[2]; o0.w = acc[i][3] + bv[3];
        o1.x = acc[i][4] + bv[4]; o1.y = acc[i][5] + bv[5];
        o1.z = acc[i][6] + bv[6]; o1.w = acc[i][7] + bv[7];
        *(float4*)cp       = o0;
        *((float4*)cp + 1) = o1;
    }
}

// ---------------------------------------------------------------------------
// Recurrent phase (R12 structure + 2-phase chunked wait).
// CTA = (dir, bblk 0..7, jb 0..7): 32j x 8b. Group = (dir, bblk), 8 producers.
// Phase A: wait flags[0..3] -> fill+matvec k[0..128).
// Phase B: wait flags[4..7] (usually set) -> fill+matvec k[128..256).
// Second-half skew hides under first-half compute. Flag released only after
// the FULL step, so the dbl-buffer safety argument is unchanged.
// ---------------------------------------------------------------------------
__global__ void __launch_bounds__(256, 1) rec_kernel(
    const float* __restrict__ U_fw,
    const float* __restrict__ U_bw,
    int layer)
{
    extern __shared__ float smem[];
    float* sU  = smem;                      // [k][jj] float4 of 4 gates: 32768 floats
    float* s_h = smem + NJ * 4 * KDIM;      // [bl][k], stride SHS

    const int cid  = blockIdx.x;
    const int dir  = cid >> 6;
    const int bblk = (cid >> 3) & 7;        // 0..7
    const int jb   = cid & 7;               // 0..7  (flag index)
    const int j0   = jb * NJ;
    const int b0   = bblk * NBL;
    const int tid  = threadIdx.x;
    const int lane = tid & 31;
    const int jl   = tid >> 3;              // 0..31
    const int bl   = tid & 7;               // 0..7
    const int j    = j0 + jl;
    const int b    = b0 + bl;

    unsigned* flags = g_flags[layer][dir * 8 + bblk];

    const float* U = dir ? U_bw : U_fw;

    // Cache U columns: sU[(k*NJ + jj)*4 + g] = U[k][g*HID + j0+jj]
    for (int idx = tid; idx < NJ * 4 * KDIM; idx += 256) {
        int g  = idx & 3;
        int jj = (idx >> 2) & (NJ - 1);
        int k  = idx >> 7;
        sU[idx] = U[(size_t)k * NCOLS + g * HID + j0 + jj];
    }
    __syncthreads();

    const unsigned a_sU = (unsigned)__cvta_generic_to_shared(sU) + (unsigned)(jl * 16);
    const float* Zd  = g_Z + (size_t)dir * MROWS * NCOLS;
    float* Hd        = (layer ? g_H2 : g_H1) + (size_t)dir * MROWS * HID;
    float* hT0 = g_hT[0][dir];              // [b][j]
    float* hT1 = g_hT[1][dir];

    // per-thread fill coords: 256 float4s per half = 8 rows x 32 cols
    const int frow = tid >> 5;              // 0..7 (batch row)
    const int fq   = tid & 31;              // float4 col within half

    // first-step Z (streamed)
    size_t zrow0 = (size_t)b * NCOLS;
    float4 z;
    z.x = __ldcs(&Zd[zrow0 + 0 * HID + j]);
    z.y = __ldcs(&Zd[zrow0 + 1 * HID + j]);
    z.z = __ldcs(&Zd[zrow0 + 2 * HID + j]);
    z.w = __ldcs(&Zd[zrow0 + 3 * HID + j]);

    float c = 0.f;

    for (int s = 0; s < TSTEPS; s++) {
        unsigned long long acc01, acc23;
        asm("mov.b64 %0,{%1,%2};" : "=l"(acc01)
            : "r"(__float_as_uint(z.x)), "r"(__float_as_uint(z.y)));
        asm("mov.b64 %0,{%1,%2};" : "=l"(acc23)
            : "r"(__float_as_uint(z.z)), "r"(__float_as_uint(z.w)));

        if (s > 0) {
            const float* src = (((s - 1) & 1) ? hT1 : hT0) + (size_t)b0 * HID;
            const float* hrow = s_h + bl * SHS;
            const unsigned tgt = (unsigned)s;

            // ===== phase A: producers 0..3 -> k[0..128) =====
            if (tid < 32) {
                while (__ballot_sync(FULLMASK,
                        (lane < 4) && (ld_acquire(&flags[lane]) < tgt))) { }
            }
            __syncthreads();
            {
                float4 v = __ldcg((const float4*)(src + frow * HID) + fq);
                *(float4*)&s_h[frow * SHS + fq * 4] = v;
            }
            __syncthreads();
#pragma unroll 16
            for (int k = 0; k < 128; k++) {
                float hv = hrow[k];
                unsigned long long hh, u01, u23;
                asm("mov.b64 %0,{%1,%1};" : "=l"(hh) : "r"(__float_as_uint(hv)));
                asm("ld.shared.v2.b64 {%0,%1},[%2];" : "=l"(u01), "=l"(u23)
                    : "r"(a_sU + (unsigned)(k * (NJ * 16))));
                asm("fma.rn.f32x2 %0,%1,%2,%0;" : "+l"(acc01) : "l"(u01), "l"(hh));
                asm("fma.rn.f32x2 %0,%1,%2,%0;" : "+l"(acc23) : "l"(u23), "l"(hh));
            }

            // ===== phase B: producers 4..7 -> k[128..256) =====
            if (tid < 32) {
                while (__ballot_sync(FULLMASK,
                        (lane < 4) && (ld_acquire(&flags[4 + lane]) < tgt))) { }
            }
            __syncthreads();
            {
                float4 v = __ldcg((const float4*)(src + frow * HID) + 32 + fq);
                *(float4*)&s_h[frow * SHS + 128 + fq * 4] = v;
            }
            __syncthreads();
#pragma unroll 16
            for (int k = 128; k < 256; k++) {
                float hv = hrow[k];
                unsigned long long hh, u01, u23;
                asm("mov.b64 %0,{%1,%1};" : "=l"(hh) : "r"(__float_as_uint(hv)));
                asm("ld.shared.v2.b64 {%0,%1},[%2];" : "=l"(u01), "=l"(u23)
                    : "r"(a_sU + (unsigned)(k * (NJ * 16))));
                asm("fma.rn.f32x2 %0,%1,%2,%0;" : "+l"(acc01) : "l"(u01), "l"(hh));
                asm("fma.rn.f32x2 %0,%1,%2,%0;" : "+l"(acc23) : "l"(u23), "l"(hh));
            }
        }

        unsigned r0, r1, r2, r3;
        asm("mov.b64 {%0,%1},%2;" : "=r"(r0), "=r"(r1) : "l"(acc01));
        asm("mov.b64 {%0,%1},%2;" : "=r"(r2), "=r"(r3) : "l"(acc23));

        float ig = fsig(__uint_as_float(r0));
        float fg = fsig(__uint_as_float(r1));
        float gg = ftanh_(__uint_as_float(r2));
        float og = fsig(__uint_as_float(r3));
        c = fg * c + ig * gg;
        float h = og * ftanh_(c);

        // publish h (dbl-buffered, [b][j]: contiguous 128B runs)
        float* hTbuf = (s & 1) ? hT1 : hT0;
        hTbuf[(size_t)b * HID + j] = h;

        __syncthreads();                      // all warps' hT stores done (HB)
        if (tid == 0 && s < TSTEPS - 1)
            st_release(&flags[jb], (unsigned)(s + 1));   // single-hop publish

        // off-critical-path: sequence output (streamed) + Z[s+1] prefetch
        __stcs(&Hd[((size_t)s * NB + b) * HID + j], h);
        if (s < TSTEPS - 1) {
            size_t zrow = ((size_t)(s + 1) * NB + b) * NCOLS;
            z.x = __ldcs(&Zd[zrow + 0 * HID + j]);
            z.y = __ldcs(&Zd[zrow + 1 * HID + j]);
            z.z = __ldcs(&Zd[zrow + 2 * HID + j]);
            z.w = __ldcs(&Zd[zrow + 3 * HID + j]);
        }
    }
}

// ---------------------------------------------------------------------------
// Output head: concat(fw, bw) @ dense_W + b, softmax over 5 classes.
// ---------------------------------------------------------------------------
__global__ void __launch_bounds__(256) dense_kernel(
    const float* __restrict__ Wd,
    const float* __restrict__ bd,
    float* __restrict__ out)
{
    __shared__ float sW[2 * HID * NCLASS];
    __shared__ float sb[NCLASS];
    const int tid = threadIdx.x;
    for (int i = tid; i < 2 * HID * NCLASS; i += 256) sW[i] = Wd[i];
    if (tid < NCLASS) sb[tid] = bd[tid];
    __syncthreads();

    int gid = blockIdx.x * 256 + tid;      // b*512 + t
    int b = gid >> 9, t = gid & 511;

    const float* hf = g_H2 + ((size_t)t * NB + b) * HID;
    const float* hb = g_H2 + (size_t)MROWS * HID + ((size_t)(TSTEPS - 1 - t) * NB + b) * HID;

    float acc[NCLASS];
#pragma unroll
    for (int cc = 0; cc < NCLASS; cc++) acc[cc] = sb[cc];

    for (int jj = 0; jj < HID; jj++) {
        float v = hf[jj];
#pragma unroll
        for (int cc = 0; cc < NCLASS; cc++)
            acc[cc] = fmaf(v, sW[jj * NCLASS + cc], acc[cc]);
    }
    for (int jj = 0; jj < HID; jj++) {
        float v = hb[jj];
#pragma unroll
        for (int cc = 0; cc < NCLASS; cc++)
            acc[cc] = fmaf(v, sW[(HID + jj) * NCLASS + cc], acc[cc]);
    }

    float m = acc[0];
#pragma unroll
    for (int cc = 1; cc < NCLASS; cc++) m = fmaxf(m, acc[cc]);
    float e[NCLASS], sum = 0.f;
#pragma unroll
    for (int cc = 0; cc < NCLASS; cc++) { e[cc] = __expf(acc[cc] - m); sum += e[cc]; }
    float inv = __fdividef(1.f, sum);
#pragma unroll
    for (int cc = 0; cc < NCLASS; cc++) out[(size_t)gid * NCLASS + cc] = e[cc] * inv;
}

// ---------------------------------------------------------------------------
// Launcher (graph-capturable: kernel launches only, default stream)
// ---------------------------------------------------------------------------
extern "C" void kernel_launch(void* const* d_in, const int* in_sizes, int n_in,
                              void* d_out, int out_size)
{
    const void*  tokens  = d_in[0];
    const float* embed   = (const float*)d_in[1];
    const float* fw_W1   = (const float*)d_in[2];
    const float* fw_U1   = (const float*)d_in[3];
    const float* fw_b1   = (const float*)d_in[4];
    const float* fw_W2   = (const float*)d_in[5];
    const float* fw_U2   = (const float*)d_in[6];
    const float* fw_b2   = (const float*)d_in[7];
    const float* bw_W1   = (const float*)d_in[8];
    const float* bw_U1   = (const float*)d_in[9];
    const float* bw_b1   = (const float*)d_in[10];
    const float* bw_W2   = (const float*)d_in[11];
    const float* bw_U2   = (const float*)d_in[12];
    const float* bw_b2   = (const float*)d_in[13];
    const float* dense_W = (const float*)d_in[14];
    const float* dense_b = (const float*)d_in[15];
    float* out = (float*)d_out;

    cudaFuncSetAttribute(rec_kernel, cudaFuncAttributeMaxDynamicSharedMemorySize, REC_SMEM);

    prep_kernel<<<1, 256>>>(tokens);

    gemm_kernel<<<dim3(8, 256, 2), 256>>>(embed, tokens, fw_W1, bw_W1, fw_b1, bw_b1, 0);
    rec_kernel<<<GRID_REC, 256, REC_SMEM>>>(fw_U1, bw_U1, 0);
    gemm_kernel<<<dim3(8, 256, 2), 256>>>(embed, tokens, fw_W2, bw_W2, fw_b2, bw_b2, 1);
    rec_kernel<<<GRID_REC, 256, REC_SMEM>>>(fw_U2, bw_U2, 1);
    dense_kernel<<<MROWS / 256, 256>>>(dense_W, dense_b, out);
}

// round 14
// speedup vs baseline: 1.1049x; 1.1049x over previous
#include <cuda_runtime.h>
#include <cstdint>

// ---------------------------------------------------------------------------
// Problem dims
// ---------------------------------------------------------------------------
#define TSTEPS 512
#define NB     64
#define HID    256
#define MROWS  (TSTEPS * NB)      // 32768
#define NCOLS  1024               // 4*HID
#define KDIM   256
#define NCLASS 5

#define GRID_REC 128
#define NJ   32                    // j per CTA
#define NBL  8                     // batches per CTA/group
#define NPROD 8                    // producers per group
#define SHS  260                   // s_h row stride (floats)
#define FULLMASK 0xffffffffu
#define REC_SMEM ((NJ * 4 * KDIM + NBL * SHS) * 4)   // 128KB U + 8.3KB h

// ---------------------------------------------------------------------------
// Scratch (static __device__ arrays: allocation-free, allowed)
// ---------------------------------------------------------------------------
__device__ __align__(128) float g_Z [2u * MROWS * NCOLS];   // gate preactivations
__device__ __align__(128) float g_H1[2u * MROWS * HID];     // layer-1 hidden outputs
__device__ __align__(128) float g_H2[2u * MROWS * HID];     // layer-2 hidden outputs
__device__ __align__(128) float g_hT[2][2][NB * HID];       // dbl-buf h, [parity][dir][b][j]
__device__ __align__(128) unsigned g_flags[2][16][NPROD];   // [layer][group][producer jb]
__device__ int g_tok32 = 1;                                 // token dtype flag

// ---------------------------------------------------------------------------
// Message passing + async-copy primitives
// ---------------------------------------------------------------------------
__device__ __forceinline__ unsigned ld_acquire(const unsigned* p) {
    unsigned v;
    asm volatile("ld.acquire.gpu.global.u32 %0, [%1];" : "=r"(v) : "l"(p) : "memory");
    return v;
}
__device__ __forceinline__ void st_release(unsigned* p, unsigned v) {
    asm volatile("st.release.gpu.global.u32 [%0], %1;" :: "l"(p), "r"(v) : "memory");
}
#define CP_ASYNC16(dst_u32, src_ptr) \
    asm volatile("cp.async.cg.shared.global [%0], [%1], 16;" :: "r"(dst_u32), "l"(src_ptr))
#define CP_COMMIT() asm volatile("cp.async.commit_group;" ::: "memory")
#define CP_WAIT0()  asm volatile("cp.async.wait_group 0;" ::: "memory")

// ---------------------------------------------------------------------------
// Math helpers
// ---------------------------------------------------------------------------
__device__ __forceinline__ float fsig(float x) {
    x = fminf(fmaxf(x, -30.f), 30.f);
    return __fdividef(1.f, 1.f + __expf(-x));
}
__device__ __forceinline__ float ftanh_(float x) {
    x = fminf(fmaxf(x, -15.f), 15.f);
    float e = __expf(-2.f * x);
    return __fdividef(1.f - e, 1.f + e);
}
__device__ __forceinline__ int load_token(const void* tokens, int is32, int idx) {
    if (is32) return ((const int*)tokens)[idx];
    return (int)((const long long*)tokens)[idx];
}

// ---------------------------------------------------------------------------
// Prep: zero flags (graph replays) + token dtype probe.
// ---------------------------------------------------------------------------
__global__ void prep_kernel(const void* __restrict__ tokens) {
    __shared__ int flag;
    const int tid = threadIdx.x;
    if (tid < 2 * 16 * NPROD) ((unsigned*)g_flags)[tid] = 0u;
    if (tid == 0) flag = 0;
    __syncthreads();
    const int* p = (const int*)tokens;
    int local = 0;
    for (int i = 1 + 2 * tid; i < MROWS; i += 2 * 256) local |= p[i];
    if (local) atomicOr(&flag, 1);
    __syncthreads();
    if (tid == 0) g_tok32 = (flag != 0) ? 1 : 0;
}

// ---------------------------------------------------------------------------
// SGEMM, software-pipelined (R13, proven 672us): C[dir] = A @ W[dir] + bias.
// B-tile: cp.async double-buffer. A-tile: register prefetch.
// ---------------------------------------------------------------------------
__global__ void __launch_bounds__(256, 2) gemm_kernel(
    const float* __restrict__ embed,
    const void*  __restrict__ tokens,
    const float* __restrict__ W_fw,
    const float* __restrict__ W_bw,
    const float* __restrict__ b_fw,
    const float* __restrict__ b_bw,
    int mode)
{
    __shared__ __align__(16) float As[2][16][132];
    __shared__ __align__(16) float Bs[2][16][128];
    __shared__ int sTok[128];

    const int tid = threadIdx.x;
    const int dir = blockIdx.z;
    const int m0  = blockIdx.y * 128;
    const int n0  = blockIdx.x * 128;

    const float* Wm   = dir ? W_bw : W_fw;
    const float* bias = dir ? b_bw : b_fw;

    if (mode == 0 && tid < 128) {
        int r = m0 + tid;
        int s = r >> 6, b = r & 63;
        int tt = (dir == 0) ? s : (TSTEPS - 1 - s);
        sTok[tid] = load_token(tokens, g_tok32, b * TSTEPS + tt);
    }
    __syncthreads();

    const int ty = tid >> 4;
    const int tx = tid & 15;

    const int am0  = tid >> 2,          akq0 = tid & 3;
    const int am1  = (tid + 256) >> 2,  akq1 = (tid + 256) & 3;
    const float* arow0;
    const float* arow1;
    if (mode == 0) {
        arow0 = embed + (size_t)sTok[am0] * KDIM;
        arow1 = embed + (size_t)sTok[am1] * KDIM;
    } else {
        const float* base = g_H1 + (size_t)dir * MROWS * HID;
        arow0 = base + (size_t)(m0 + am0) * HID;
        arow1 = base + (size_t)(m0 + am1) * HID;
    }

    const int bk0 = tid >> 5,          bn0 = tid & 31;
    const int bk1 = (tid + 256) >> 5,  bn1 = (tid + 256) & 31;
    const uint32_t bs0_base = (uint32_t)__cvta_generic_to_shared(&Bs[0][bk0][bn0 * 4]);
    const uint32_t bs1_base = (uint32_t)__cvta_generic_to_shared(&Bs[0][bk1][bn1 * 4]);
    const uint32_t bufstride = (uint32_t)(16 * 128 * 4);
    const float* bsrc0 = Wm + (size_t)bk0 * NCOLS + n0 + bn0 * 4;
    const float* bsrc1 = Wm + (size_t)bk1 * NCOLS + n0 + bn1 * 4;

    float acc[8][8];
#pragma unroll
    for (int i = 0; i < 8; i++)
#pragma unroll
        for (int j = 0; j < 8; j++) acc[i][j] = 0.f;

    CP_ASYNC16(bs0_base, bsrc0);
    CP_ASYNC16(bs1_base, bsrc1);
    CP_COMMIT();
    {
        float4 a0 = *(const float4*)(arow0 + akq0 * 4);
        float4 a1 = *(const float4*)(arow1 + akq1 * 4);
        As[0][akq0 * 4 + 0][am0] = a0.x; As[0][akq0 * 4 + 1][am0] = a0.y;
        As[0][akq0 * 4 + 2][am0] = a0.z; As[0][akq0 * 4 + 3][am0] = a0.w;
        As[0][akq1 * 4 + 0][am1] = a1.x; As[0][akq1 * 4 + 1][am1] = a1.y;
        As[0][akq1 * 4 + 2][am1] = a1.z; As[0][akq1 * 4 + 3][am1] = a1.w;
    }
    CP_WAIT0();
    __syncthreads();

    for (int t = 0; t < 16; t++) {
        const int buf  = t & 1;
        const int nbuf = buf ^ 1;
        float4 a0, a1;
        const bool more = (t + 1 < 16);
        if (more) {
            const int kt = (t + 1) * 16;
            CP_ASYNC16(bs0_base + (uint32_t)nbuf * bufstride, bsrc0 + (size_t)kt * NCOLS);
            CP_ASYNC16(bs1_base + (uint32_t)nbuf * bufstride, bsrc1 + (size_t)kt * NCOLS);
            CP_COMMIT();
            a0 = *(const float4*)(arow0 + kt + akq0 * 4);
            a1 = *(const float4*)(arow1 + kt + akq1 * 4);
        }

#pragma unroll
        for (int kk = 0; kk < 16; kk++) {
            float a[8], bb[8];
            *(float4*)&a[0]  = *(const float4*)&As[buf][kk][ty * 8];
            *(float4*)&a[4]  = *(const float4*)&As[buf][kk][ty * 8 + 4];
            *(float4*)&bb[0] = *(const float4*)&Bs[buf][kk][tx * 8];
            *(float4*)&bb[4] = *(const float4*)&Bs[buf][kk][tx * 8 + 4];
#pragma unroll
            for (int i = 0; i < 8; i++)
#pragma unroll
                for (int j = 0; j < 8; j++)
                    acc[i][j] = fmaf(a[i], bb[j], acc[i][j]);
        }

        if (more) {
            As[nbuf][akq0 * 4 + 0][am0] = a0.x; As[nbuf][akq0 * 4 + 1][am0] = a0.y;
            As[nbuf][akq0 * 4 + 2][am0] = a0.z; As[nbuf][akq0 * 4 + 3][am0] = a0.w;
            As[nbuf][akq1 * 4 + 0][am1] = a1.x; As[nbuf][akq1 * 4 + 1][am1] = a1.y;
            As[nbuf][akq1 * 4 + 2][am1] = a1.z; As[nbuf][akq1 * 4 + 3][am1] = a1.w;
            CP_WAIT0();
        }
        __syncthreads();
    }

    float bv[8];
#pragma unroll
    for (int j = 0; j < 8; j++) bv[j] = bias[n0 + tx * 8 + j];

    float* Cd = g_Z + (size_t)dir * MROWS * NCOLS;
#pragma unroll
    for (int i = 0; i < 8; i++) {
        size_t r = (size_t)(m0 + ty * 8 + i);
        float* cp = Cd + r * NCOLS + n0 + tx * 8;
        float4 o0, o1;
        o0.x = acc[i][0] + bv[0]; o0.y = acc[i][1] + bv[1];
        o0.z = acc[i][2] + bv[2]; o0.w = acc[i][3] + bv[3];
        o1.x = acc[i][4] + bv[4]; o1.y = acc[i][5] + bv[5];
        o1.z = acc[i][6] + bv[6]; o1.w = acc[i][7] + bv[7];
        *(float4*)cp       = o0;
        *((float4*)cp + 1) = o1;
    }
}

// ---------------------------------------------------------------------------
// Recurrent phase — R12 VERBATIM (proven 4.9us tick; R13's chunked wait
// regressed and is reverted). CTA = (dir, bblk 0..7, jb 0..7): 32j x 8b.
// Group = (dir, bblk), 8 producers, flags in one 32B sector, 8KB coalesced
// fill, [b][j] contiguous publish. Warp-0 acquire-poll + single release.
// ---------------------------------------------------------------------------
__global__ void __launch_bounds__(256, 1) rec_kernel(
    const float* __restrict__ U_fw,
    const float* __restrict__ U_bw,
    int layer)
{
    extern __shared__ float smem[];
    float* sU  = smem;                      // [k][jj] float4 of 4 gates: 32768 floats
    float* s_h = smem + NJ * 4 * KDIM;      // [bl][k], stride SHS

    const int cid  = blockIdx.x;
    const int dir  = cid >> 6;
    const int bblk = (cid >> 3) & 7;        // 0..7
    const int jb   = cid & 7;               // 0..7  (this CTA's flag index)
    const int j0   = jb * NJ;
    const int b0   = bblk * NBL;
    const int tid  = threadIdx.x;
    const int lane = tid & 31;
    const int jl   = tid >> 3;              // 0..31
    const int bl   = tid & 7;               // 0..7
    const int j    = j0 + jl;
    const int b    = b0 + bl;

    unsigned* flags = g_flags[layer][dir * 8 + bblk];

    const float* U = dir ? U_bw : U_fw;

    // Cache U columns: sU[(k*NJ + jj)*4 + g] = U[k][g*HID + j0+jj]
    for (int idx = tid; idx < NJ * 4 * KDIM; idx += 256) {
        int g  = idx & 3;
        int jj = (idx >> 2) & (NJ - 1);
        int k  = idx >> 7;
        sU[idx] = U[(size_t)k * NCOLS + g * HID + j0 + jj];
    }
    __syncthreads();

    const unsigned a_sU = (unsigned)__cvta_generic_to_shared(sU) + (unsigned)(jl * 16);
    const float* Zd  = g_Z + (size_t)dir * MROWS * NCOLS;
    float* Hd        = (layer ? g_H2 : g_H1) + (size_t)dir * MROWS * HID;
    float* hT0 = g_hT[0][dir];              // [b][j]
    float* hT1 = g_hT[1][dir];

    // first-step Z (streamed)
    size_t zrow0 = (size_t)b * NCOLS;
    float4 z;
    z.x = __ldcs(&Zd[zrow0 + 0 * HID + j]);
    z.y = __ldcs(&Zd[zrow0 + 1 * HID + j]);
    z.z = __ldcs(&Zd[zrow0 + 2 * HID + j]);
    z.w = __ldcs(&Zd[zrow0 + 3 * HID + j]);

    float c = 0.f;

    for (int s = 0; s < TSTEPS; s++) {
        unsigned long long acc01, acc23;
        asm("mov.b64 %0,{%1,%2};" : "=l"(acc01)
            : "r"(__float_as_uint(z.x)), "r"(__float_as_uint(z.y)));
        asm("mov.b64 %0,{%1,%2};" : "=l"(acc23)
            : "r"(__float_as_uint(z.z)), "r"(__float_as_uint(z.w)));

        if (s > 0) {
            // ---- wait: warp 0 polls the 8 producer flags (one 32B sector)
            if (tid < 32) {
                const unsigned tgt = (unsigned)s;
                while (__ballot_sync(FULLMASK,
                        (lane < NPROD) && (ld_acquire(&flags[lane]) < tgt))) { }
            }
            __syncthreads();                 // release warps 1-7; acquire HB

            // ---- fill s_h[bl][k] from g_hT[(s-1)&1][b0..b0+8)[0..256) (coalesced)
            const float* src = (((s - 1) & 1) ? hT1 : hT0) + (size_t)b0 * HID;
#pragma unroll
            for (int i = 0; i < 2; i++) {
                int idx = tid + i * 256;            // 0..511 float4s
                int row = idx >> 6;                 // 0..7 (batch)
                int q   = idx & 63;                 // float4 col
                float4 v = __ldcg((const float4*)(src + row * HID) + q);
                *(float4*)&s_h[row * SHS + q * 4] = v;
            }
            __syncthreads();

            // ---- matvec: z += h @ U (FFMA2)
            const float* hrow = s_h + bl * SHS;
#pragma unroll 16
            for (int k = 0; k < KDIM; k++) {
                float hv = hrow[k];
                unsigned long long hh, u01, u23;
                asm("mov.b64 %0,{%1,%1};" : "=l"(hh) : "r"(__float_as_uint(hv)));
                asm("ld.shared.v2.b64 {%0,%1},[%2];" : "=l"(u01), "=l"(u23)
                    : "r"(a_sU + (unsigned)(k * (NJ * 16))));
                asm("fma.rn.f32x2 %0,%1,%2,%0;" : "+l"(acc01) : "l"(u01), "l"(hh));
                asm("fma.rn.f32x2 %0,%1,%2,%0;" : "+l"(acc23) : "l"(u23), "l"(hh));
            }
        }

        unsigned r0, r1, r2, r3;
        asm("mov.b64 {%0,%1},%2;" : "=r"(r0), "=r"(r1) : "l"(acc01));
        asm("mov.b64 {%0,%1},%2;" : "=r"(r2), "=r"(r3) : "l"(acc23));

        float ig = fsig(__uint_as_float(r0));
        float fg = fsig(__uint_as_float(r1));
        float gg = ftanh_(__uint_as_float(r2));
        float og = fsig(__uint_as_float(r3));
        c = fg * c + ig * gg;
        float h = og * ftanh_(c);

        // publish h for next step (dbl-buffered, [b][j]: 8x128B runs)
        float* hTbuf = (s & 1) ? hT1 : hT0;
        hTbuf[(size_t)b * HID + j] = h;

        __syncthreads();                      // all warps' hT stores done (HB)
        if (tid == 0 && s < TSTEPS - 1)
            st_release(&flags[jb], (unsigned)(s + 1));   // single-hop publish

        // off-critical-path: sequence output (streamed) + Z[s+1] prefetch
        __stcs(&Hd[((size_t)s * NB + b) * HID + j], h);
        if (s < TSTEPS - 1) {
            size_t zrow = ((size_t)(s + 1) * NB + b) * NCOLS;
            z.x = __ldcs(&Zd[zrow + 0 * HID + j]);
            z.y = __ldcs(&Zd[zrow + 1 * HID + j]);
            z.z = __ldcs(&Zd[zrow + 2 * HID + j]);
            z.w = __ldcs(&Zd[zrow + 3 * HID + j]);
        }
    }
}

// ---------------------------------------------------------------------------
// Output head: concat(fw, bw) @ dense_W + b, softmax over 5 classes.
// ---------------------------------------------------------------------------
__global__ void __launch_bounds__(256) dense_kernel(
    const float* __restrict__ Wd,
    const float* __restrict__ bd,
    float* __restrict__ out)
{
    __shared__ float sW[2 * HID * NCLASS];
    __shared__ float sb[NCLASS];
    const int tid = threadIdx.x;
    for (int i = tid; i < 2 * HID * NCLASS; i += 256) sW[i] = Wd[i];
    if (tid < NCLASS) sb[tid] = bd[tid];
    __syncthreads();

    int gid = blockIdx.x * 256 + tid;      // b*512 + t
    int b = gid >> 9, t = gid & 511;

    const float* hf = g_H2 + ((size_t)t * NB + b) * HID;
    const float* hb = g_H2 + (size_t)MROWS * HID + ((size_t)(TSTEPS - 1 - t) * NB + b) * HID;

    float acc[NCLASS];
#pragma unroll
    for (int cc = 0; cc < NCLASS; cc++) acc[cc] = sb[cc];

    for (int jj = 0; jj < HID; jj++) {
        float v = hf[jj];
#pragma unroll
        for (int cc = 0; cc < NCLASS; cc++)
            acc[cc] = fmaf(v, sW[jj * NCLASS + cc], acc[cc]);
    }
    for (int jj = 0; jj < HID; jj++) {
        float v = hb[jj];
#pragma unroll
        for (int cc = 0; cc < NCLASS; cc++)
            acc[cc] = fmaf(v, sW[(HID + jj) * NCLASS + cc], acc[cc]);
    }

    float m = acc[0];
#pragma unroll
    for (int cc = 1; cc < NCLASS; cc++) m = fmaxf(m, acc[cc]);
    float e[NCLASS], sum = 0.f;
#pragma unroll
    for (int cc = 0; cc < NCLASS; cc++) { e[cc] = __expf(acc[cc] - m); sum += e[cc]; }
    float inv = __fdividef(1.f, sum);
#pragma unroll
    for (int cc = 0; cc < NCLASS; cc++) out[(size_t)gid * NCLASS + cc] = e[cc] * inv;
}

// ---------------------------------------------------------------------------
// Launcher (graph-capturable: kernel launches only, default stream)
// ---------------------------------------------------------------------------
extern "C" void kernel_launch(void* const* d_in, const int* in_sizes, int n_in,
                              void* d_out, int out_size)
{
    const void*  tokens  = d_in[0];
    const float* embed   = (const float*)d_in[1];
    const float* fw_W1   = (const float*)d_in[2];
    const float* fw_U1   = (const float*)d_in[3];
    const float* fw_b1   = (const float*)d_in[4];
    const float* fw_W2   = (const float*)d_in[5];
    const float* fw_U2   = (const float*)d_in[6];
    const float* fw_b2   = (const float*)d_in[7];
    const float* bw_W1   = (const float*)d_in[8];
    const float* bw_U1   = (const float*)d_in[9];
    const float* bw_b1   = (const float*)d_in[10];
    const float* bw_W2   = (const float*)d_in[11];
    const float* bw_U2   = (const float*)d_in[12];
    const float* bw_b2   = (const float*)d_in[13];
    const float* dense_W = (const float*)d_in[14];
    const float* dense_b = (const float*)d_in[15];
    float* out = (float*)d_out;

    cudaFuncSetAttribute(rec_kernel, cudaFuncAttributeMaxDynamicSharedMemorySize, REC_SMEM);

    prep_kernel<<<1, 256>>>(tokens);

    gemm_kernel<<<dim3(8, 256, 2), 256>>>(embed, tokens, fw_W1, bw_W1, fw_b1, bw_b1, 0);
    rec_kernel<<<GRID_REC, 256, REC_SMEM>>>(fw_U1, bw_U1, 0);
    gemm_kernel<<<dim3(8, 256, 2), 256>>>(embed, tokens, fw_W2, bw_W2, fw_b2, bw_b2, 1);
    rec_kernel<<<GRID_REC, 256, REC_SMEM>>>(fw_U2, bw_U2, 1);
    dense_kernel<<<MROWS / 256, 256>>>(dense_W, dense_b, out);
}